// round 9
// baseline (speedup 1.0000x reference)
#include <cuda_runtime.h>

#define H 32
#define WPB 16          // warps per block; 1 batch row per warp
#define THREADS (WPB*32)
#define CHUNK 16        // deferred-output chunk

typedef unsigned long long ull;

// ---------- packed f32x2 helpers (sm_103a dual FP32 pipe) ----------
__device__ __forceinline__ ull ffma2(ull a, ull b, ull c) {
    ull d;
    asm("fma.rn.f32x2 %0, %1, %2, %3;" : "=l"(d) : "l"(a), "l"(b), "l"(c));
    return d;
}
__device__ __forceinline__ ull addf2(ull a, ull b) {
    ull d;
    asm("add.rn.f32x2 %0, %1, %2;" : "=l"(d) : "l"(a), "l"(b));
    return d;
}
__device__ __forceinline__ ull mulf2(ull a, ull b) {
    ull d;
    asm("mul.rn.f32x2 %0, %1, %2;" : "=l"(d) : "l"(a), "l"(b));
    return d;
}
__device__ __forceinline__ float hsum2(ull a) {
    float lo, hi;
    asm("mov.b64 {%0, %1}, %2;" : "=f"(lo), "=f"(hi) : "l"(a));
    return lo + hi;
}
__device__ __forceinline__ float tanh_ap(float x) {
    float r; asm("tanh.approx.f32 %0, %1;" : "=f"(r) : "f"(x)); return r;
}
__device__ __forceinline__ ull pack2(float lo, float hi) {
    ull d;
    asm("mov.b64 %0, {%1, %2};" : "=l"(d) : "f"(lo), "f"(hi));
    return d;
}

// One warp = one batch row, lane = hidden unit. 16 warps/block, grid=128:
// 4 warps/SMSP for latency hiding, perfectly balanced, single wave.
__global__ void __launch_bounds__(THREADS, 1)
gru_warp_kernel(const float* __restrict__ x,     // [B,T]
                const float* __restrict__ h0,    // [B,H]
                const float* __restrict__ W_ih,  // [3H] (I=1)
                const float* __restrict__ W_hh,  // [3H,H]
                const float* __restrict__ b_ih,  // [3H]
                const float* __restrict__ b_hh,  // [3H]
                const float* __restrict__ W_out, // [H]
                const float* __restrict__ b_out, // [1]
                float* __restrict__ y,           // [B,T]
                float* __restrict__ hn,          // [B,H]
                int B, int T)
{
    __shared__ __align__(16) float ring[WPB][2][H];      // double-buffered h bcast
    __shared__ float hT[WPB][H][CHUNK + 1];              // transposed step history
    __shared__ float wout_s[H + 1];                      // [32]=b_out

    const int lane = threadIdx.x & 31;   // hidden unit u
    const int w    = threadIdx.x >> 5;
    const int b    = blockIdx.x * WPB + w;

    if (threadIdx.x < H) wout_s[threadIdx.x] = W_out[threadIdx.x];
    if (threadIdx.x == H) wout_s[H] = b_out[0];
    __syncthreads();
    if (b >= B) return;

    // ---- recurrent weights for unit u (3 gate rows), packed k-pairs.
    //      r/z rows pre-scaled by 0.5: sigmoid(a) = 0.5 + 0.5*tanh(a/2). ----
    ull Wr[16], Wz[16], Wn[16];
    {
        const ull HALF2 = 0x3F0000003F000000ull;  // (0.5f, 0.5f)
        const ull* wr = (const ull*)(W_hh + (size_t)lane * H);
        const ull* wz = (const ull*)(W_hh + (size_t)(H + lane) * H);
        const ull* wn = (const ull*)(W_hh + (size_t)(2 * H + lane) * H);
        #pragma unroll
        for (int k = 0; k < 16; k++) {
            Wr[k] = mulf2(wr[k], HALF2);
            Wz[k] = mulf2(wz[k], HALF2);
            Wn[k] = wn[k];
        }
    }
    const float wihr = 0.5f * W_ih[lane];
    const float wihz = 0.5f * W_ih[H + lane];
    const float wihn = W_ih[2 * H + lane];
    // gate biases folded into accumulator inits (lo half of packed pair)
    const ull ir  = pack2(0.5f * (b_ih[lane] + b_hh[lane]), 0.0f);
    const ull iz  = pack2(0.5f * (b_ih[H + lane] + b_hh[H + lane]), 0.0f);
    const ull in_ = pack2(b_hh[2 * H + lane], 0.0f);  // n hidden bias (inside r*)
    const float bin = b_ih[2 * H + lane];

    float h = h0[(size_t)b * H + lane];
    ring[w][1][lane] = h;     // step 0 reads parity 1
    __syncwarp();

    const float* xrow = x + (size_t)b * T;
    float*       yrow = y + (size_t)b * T;

    const int tl = lane & 15;            // timestep duty in x-stage / y-phase
    const int jb = lane & 16;            // half of H this lane accumulates in y

    for (int t0 = 0; t0 < T; t0 += CHUNK) {
        const float xv = xrow[t0 + tl];  // 16 steps of input staged (dup hi half)

        #pragma unroll 2
        for (int s = 0; s < CHUNK; s++) {
            const int rd = (s & 1) ^ 1;
            const int wb = (s & 1);

            const float xt = __shfl_sync(0xffffffffu, xv, s);   // issue early

            const ulonglong2* hp = (const ulonglong2*)&ring[w][rd][0];
            // 6 independent 8-deep FFMA2 chains
            ull ar0 = ir,  az0 = iz,  an0 = in_;
            ull ar1 = 0ull, az1 = 0ull, an1 = 0ull;
            #pragma unroll
            for (int q = 0; q < 8; q++) {
                const ulonglong2 hv = hp[q];   // 4 h values (broadcast LDS.128)
                ar0 = ffma2(hv.x, Wr[2 * q],     ar0);
                az0 = ffma2(hv.x, Wz[2 * q],     az0);
                an0 = ffma2(hv.x, Wn[2 * q],     an0);
                ar1 = ffma2(hv.y, Wr[2 * q + 1], ar1);
                az1 = ffma2(hv.y, Wz[2 * q + 1], az1);
                an1 = ffma2(hv.y, Wn[2 * q + 1], an1);
            }
            const float gr = hsum2(addf2(ar0, ar1));
            const float gz = hsum2(addf2(az0, az1));
            const float gn = hsum2(addf2(an0, an1));

            const float rg = fmaf(0.5f, tanh_ap(fmaf(xt, wihr, gr)), 0.5f);
            const float zg = fmaf(0.5f, tanh_ap(fmaf(xt, wihz, gz)), 0.5f);
            const float ng = tanh_ap(fmaf(rg, gn, fmaf(xt, wihn, bin)));
            h = fmaf(zg, h - ng, ng);          // (1-z)*n + z*h

            ring[w][wb][lane] = h;             // broadcast for next step
            hT[w][lane][s]    = h;             // history for deferred y matvec
            __syncwarp();
        }

        // Deferred y: half-warp split over H; lanes 0..15 store steps 0..15.
        // addr = (jb+k)*17 + tl -> all 32 lanes distinct banks for each k.
        float acc = 0.0f;
        #pragma unroll
        for (int k = 0; k < 16; k++)
            acc = fmaf(hT[w][jb + k][tl], wout_s[jb + k], acc);
        acc += __shfl_xor_sync(0xffffffffu, acc, 16);
        if (lane < 16) yrow[t0 + tl] = acc + wout_s[H];   // 64B coalesced
        __syncwarp();                                      // hT WAR next chunk
    }

    hn[(size_t)b * H + lane] = h;
}

extern "C" void kernel_launch(void* const* d_in, const int* in_sizes, int n_in,
                              void* d_out, int out_size) {
    const float* x     = (const float*)d_in[0];   // [B,T,1]
    const float* h0    = (const float*)d_in[1];   // [1,B,H]
    const float* W_ih  = (const float*)d_in[2];   // [3H,1]
    const float* W_hh  = (const float*)d_in[3];   // [3H,H]
    const float* b_ih  = (const float*)d_in[4];   // [3H]
    const float* b_hh  = (const float*)d_in[5];   // [3H]
    const float* W_out = (const float*)d_in[6];   // [1,H]
    const float* b_out = (const float*)d_in[7];   // [1]
    float* out = (float*)d_out;

    const int B = in_sizes[1] / H;                // 2048
    const int T = in_sizes[0] / B;                // 1024

    float* y  = out;                              // [B,T]
    float* hn = out + (size_t)B * T;              // [B,H]

    const int grid = (B + WPB - 1) / WPB;         // 128: balanced, single wave
    gru_warp_kernel<<<grid, THREADS>>>(x, h0, W_ih, W_hh, b_ih, b_hh,
                                       W_out, b_out, y, hn, B, T);
}

// round 10
// speedup vs baseline: 1.0544x; 1.0544x over previous
#include <cuda_runtime.h>

#define H 32
#define WPB 7           // warps per block; each warp = 2 batch rows
#define THREADS (WPB*32)
#define CHUNK 16        // deferred-output chunk
#define RSTRIDE 48      // ring: row B offset (floats) -> 16-bank shift
#define TSTRIDE 560     // hT: row B offset (floats), 560%32==16 -> 16-bank shift

typedef unsigned long long ull;

// compiler-only ordering fence: no instruction, stops smem reorder/caching
#define CFENCE() asm volatile("" ::: "memory")

// ---------- packed f32x2 helpers (sm_103a dual FP32 pipe) ----------
__device__ __forceinline__ ull ffma2(ull a, ull b, ull c) {
    ull d;
    asm("fma.rn.f32x2 %0, %1, %2, %3;" : "=l"(d) : "l"(a), "l"(b), "l"(c));
    return d;
}
__device__ __forceinline__ ull mulf2(ull a, ull b) {
    ull d;
    asm("mul.rn.f32x2 %0, %1, %2;" : "=l"(d) : "l"(a), "l"(b));
    return d;
}
__device__ __forceinline__ float hsum2(ull a) {
    float lo, hi;
    asm("mov.b64 {%0, %1}, %2;" : "=f"(lo), "=f"(hi) : "l"(a));
    return lo + hi;
}
__device__ __forceinline__ float tanh_ap(float x) {
    float r; asm("tanh.approx.f32 %0, %1;" : "=f"(r) : "f"(x)); return r;
}
__device__ __forceinline__ ull pack2(float lo, float hi) {
    ull d;
    asm("mov.b64 %0, {%1, %2};" : "=l"(d) : "f"(lo), "f"(hi));
    return d;
}

// One warp = 2 batch rows (half-warp per row); lane owns hidden units u0, u0+16
// of its row. All hot-loop smem is warp-private and the loop is branch-
// convergent, so no __syncwarp is needed — compiler fences only.
// grid=147 x 7 warps covers 1024 row-pairs, single wave, all SMs.
__global__ void __launch_bounds__(THREADS, 1)
gru_warp_kernel(const float* __restrict__ x,     // [B,T]
                const float* __restrict__ h0,    // [B,H]
                const float* __restrict__ W_ih,  // [3H] (I=1)
                const float* __restrict__ W_hh,  // [3H,H]
                const float* __restrict__ b_ih,  // [3H]
                const float* __restrict__ b_hh,  // [3H]
                const float* __restrict__ W_out, // [H]
                const float* __restrict__ b_out, // [1]
                float* __restrict__ y,           // [B,T]
                float* __restrict__ hn,          // [B,H]
                int B, int T)
{
    __shared__ __align__(16) float ring[WPB][2][2 * RSTRIDE]; // double-buffered h, 2 rows
    __shared__ float hT[WPB][2][TSTRIDE];                     // per-row 32x17 history
    __shared__ float wout_s[H + 1];                           // [32]=b_out

    const int lane = threadIdx.x & 31;
    const int w    = threadIdx.x >> 5;
    const int npairs = B >> 1;
    const int p    = blockIdx.x * WPB + w;

    if (threadIdx.x < H) wout_s[threadIdx.x] = W_out[threadIdx.x];
    if (threadIdx.x == H) wout_s[H] = b_out[0];
    __syncthreads();
    if (p >= npairs) return;

    const int u0  = lane & 15;     // first hidden unit this lane owns
    const int r   = lane >> 4;     // which row of the pair this half-warp runs
    const int row = 2 * p + r;     // global batch row

    // ---- recurrent weights for units u0 and u0+16 (6 gate rows), packed pairs.
    //      r/z rows pre-scaled by 0.5: sigmoid(a) = 0.5 + 0.5*tanh(a/2). ----
    ull Wr0[16], Wz0[16], Wn0[16], Wr1[16], Wz1[16], Wn1[16];
    {
        const ull HALF2 = 0x3F0000003F000000ull;  // (0.5f, 0.5f)
        const int u1 = u0 + 16;
        const ull* wr0 = (const ull*)(W_hh + (size_t)u0 * H);
        const ull* wz0 = (const ull*)(W_hh + (size_t)(H + u0) * H);
        const ull* wn0 = (const ull*)(W_hh + (size_t)(2 * H + u0) * H);
        const ull* wr1 = (const ull*)(W_hh + (size_t)u1 * H);
        const ull* wz1 = (const ull*)(W_hh + (size_t)(H + u1) * H);
        const ull* wn1 = (const ull*)(W_hh + (size_t)(2 * H + u1) * H);
        #pragma unroll
        for (int k = 0; k < 16; k++) {
            Wr0[k] = mulf2(wr0[k], HALF2);
            Wz0[k] = mulf2(wz0[k], HALF2);
            Wn0[k] = wn0[k];
            Wr1[k] = mulf2(wr1[k], HALF2);
            Wz1[k] = mulf2(wz1[k], HALF2);
            Wn1[k] = wn1[k];
        }
    }
    const int u1 = u0 + 16;
    const float wihr0 = 0.5f * W_ih[u0],    wihr1 = 0.5f * W_ih[u1];
    const float wihz0 = 0.5f * W_ih[H + u0], wihz1 = 0.5f * W_ih[H + u1];
    const float wihn0 = W_ih[2 * H + u0],   wihn1 = W_ih[2 * H + u1];
    // ALL gate biases folded into accumulator inits (lo half of packed pair)
    const ull ir0 = pack2(0.5f * (b_ih[u0] + b_hh[u0]), 0.0f);
    const ull ir1 = pack2(0.5f * (b_ih[u1] + b_hh[u1]), 0.0f);
    const ull iz0 = pack2(0.5f * (b_ih[H + u0] + b_hh[H + u0]), 0.0f);
    const ull iz1 = pack2(0.5f * (b_ih[H + u1] + b_hh[H + u1]), 0.0f);
    const ull in0 = pack2(b_hh[2 * H + u0], 0.0f);   // n hidden bias (inside r*)
    const ull in1 = pack2(b_hh[2 * H + u1], 0.0f);
    const float bin0 = b_ih[2 * H + u0], bin1 = b_ih[2 * H + u1];

    float hA = h0[(size_t)row * H + u0];
    float hB = h0[(size_t)row * H + u1];
    ring[w][1][r * RSTRIDE + u0] = hA;     // step 0 reads parity 1
    ring[w][1][r * RSTRIDE + u1] = hB;
    CFENCE();

    const float* xrow = x + (size_t)row * T;
    float*       yrow = y + (size_t)row * T;
    float* hTrow = &hT[w][r][0];

    for (int t0 = 0; t0 < T; t0 += CHUNK) {
        const float xv = xrow[t0 + u0];   // lane u0==t stages this row's inputs

        float xt = __shfl_sync(0xffffffffu, xv, 0, 16);  // step 0 prefetch

        #pragma unroll 2
        for (int s = 0; s < CHUNK; s++) {
            const int rd = (s & 1) ^ 1;
            const int wb = (s & 1);

            // prefetch next step's xt: 26-cyc shfl hidden under the dot product
            const float xt_nx = __shfl_sync(0xffffffffu, xv, (s + 1) & 15, 16);

            const ulonglong2* hp = (const ulonglong2*)&ring[w][rd][r * RSTRIDE];
            ull ar0 = ir0, az0 = iz0, an0 = in0;
            ull ar1 = ir1, az1 = iz1, an1 = in1;
            #pragma unroll
            for (int q = 0; q < 8; q++) {
                const ulonglong2 hv = hp[q];     // 4 h values of this row
                ar0 = ffma2(hv.x, Wr0[2 * q],     ar0);
                az0 = ffma2(hv.x, Wz0[2 * q],     az0);
                an0 = ffma2(hv.x, Wn0[2 * q],     an0);
                ar1 = ffma2(hv.x, Wr1[2 * q],     ar1);
                az1 = ffma2(hv.x, Wz1[2 * q],     az1);
                an1 = ffma2(hv.x, Wn1[2 * q],     an1);
                ar0 = ffma2(hv.y, Wr0[2 * q + 1], ar0);
                az0 = ffma2(hv.y, Wz0[2 * q + 1], az0);
                an0 = ffma2(hv.y, Wn0[2 * q + 1], an0);
                ar1 = ffma2(hv.y, Wr1[2 * q + 1], ar1);
                az1 = ffma2(hv.y, Wz1[2 * q + 1], az1);
                an1 = ffma2(hv.y, Wn1[2 * q + 1], an1);
            }
            // unit u0
            {
                const float rg = fmaf(0.5f, tanh_ap(fmaf(xt, wihr0, hsum2(ar0))), 0.5f);
                const float zg = fmaf(0.5f, tanh_ap(fmaf(xt, wihz0, hsum2(az0))), 0.5f);
                const float ng = tanh_ap(fmaf(rg, hsum2(an0), fmaf(xt, wihn0, bin0)));
                hA = fmaf(zg, hA - ng, ng);
            }
            // unit u0+16
            {
                const float rg = fmaf(0.5f, tanh_ap(fmaf(xt, wihr1, hsum2(ar1))), 0.5f);
                const float zg = fmaf(0.5f, tanh_ap(fmaf(xt, wihz1, hsum2(az1))), 0.5f);
                const float ng = tanh_ap(fmaf(rg, hsum2(an1), fmaf(xt, wihn1, bin1)));
                hB = fmaf(zg, hB - ng, ng);
            }

            ring[w][wb][r * RSTRIDE + u0] = hA;
            ring[w][wb][r * RSTRIDE + u1] = hB;
            hTrow[17 * u0 + s] = hA;          // conflict-free (derived bank map)
            hTrow[17 * u1 + s] = hB;
            CFENCE();                          // same-warp in-order MIO: no sync

            xt = xt_nx;
        }

        // Deferred y: every lane produces one output (row r, timestep u0).
        float acc = 0.0f;
        #pragma unroll
        for (int j = 0; j < H; j++)
            acc = fmaf(hTrow[17 * j + u0], wout_s[j], acc);
        yrow[t0 + u0] = acc + wout_s[H];      // 2x64B coalesced, all lanes
        CFENCE();                              // hT WAR before next chunk
    }

    hn[(size_t)row * H + u0] = hA;
    hn[(size_t)row * H + u1] = hB;
}

extern "C" void kernel_launch(void* const* d_in, const int* in_sizes, int n_in,
                              void* d_out, int out_size) {
    const float* x     = (const float*)d_in[0];   // [B,T,1]
    const float* h0    = (const float*)d_in[1];   // [1,B,H]
    const float* W_ih  = (const float*)d_in[2];   // [3H,1]
    const float* W_hh  = (const float*)d_in[3];   // [3H,H]
    const float* b_ih  = (const float*)d_in[4];   // [3H]
    const float* b_hh  = (const float*)d_in[5];   // [3H]
    const float* W_out = (const float*)d_in[6];   // [1,H]
    const float* b_out = (const float*)d_in[7];   // [1]
    float* out = (float*)d_out;

    const int B = in_sizes[1] / H;                // 2048
    const int T = in_sizes[0] / B;                // 1024

    float* y  = out;                              // [B,T]
    float* hn = out + (size_t)B * T;              // [B,H]

    const int npairs = B / 2;                     // 1024
    const int grid = (npairs + WPB - 1) / WPB;    // 147 -> all SMs, single wave
    gru_warp_kernel<<<grid, THREADS>>>(x, h0, W_ih, W_hh, b_ih, b_hh,
                                       W_out, b_out, y, hn, B, T);
}

// round 11
// speedup vs baseline: 1.1193x; 1.0615x over previous
#include <cuda_runtime.h>

#define H 32
#define WPB 7           // warps per block; each warp = 2 batch rows
#define THREADS (WPB*32)
#define CHUNK 16        // deferred-output chunk
#define RSTRIDE 48      // ring: row B offset (floats) -> 16-bank shift
#define TSTRIDE 560     // hT: row B offset (floats), 560%32==16 -> 16-bank shift

typedef unsigned long long ull;

// ---------- packed f32x2 helpers (sm_103a dual FP32 pipe) ----------
__device__ __forceinline__ ull ffma2(ull a, ull b, ull c) {
    ull d;
    asm("fma.rn.f32x2 %0, %1, %2, %3;" : "=l"(d) : "l"(a), "l"(b), "l"(c));
    return d;
}
__device__ __forceinline__ ull mulf2(ull a, ull b) {
    ull d;
    asm("mul.rn.f32x2 %0, %1, %2;" : "=l"(d) : "l"(a), "l"(b));
    return d;
}
__device__ __forceinline__ float hsum2(ull a) {
    float lo, hi;
    asm("mov.b64 {%0, %1}, %2;" : "=f"(lo), "=f"(hi) : "l"(a));
    return lo + hi;
}
__device__ __forceinline__ float tanh_ap(float x) {
    float r; asm("tanh.approx.f32 %0, %1;" : "=f"(r) : "f"(x)); return r;
}
__device__ __forceinline__ ull pack2(float lo, float hi) {
    ull d;
    asm("mov.b64 %0, {%1, %2};" : "=l"(d) : "f"(lo), "f"(hi));
    return d;
}

// One warp = 2 batch rows (half-warp per row); lane owns hidden units u0, u0+16
// of its row. grid=147 x 7 warps covers 1024 row-pairs, single wave, all SMs.
__global__ void __launch_bounds__(THREADS, 1)
gru_warp_kernel(const float* __restrict__ x,     // [B,T]
                const float* __restrict__ h0,    // [B,H]
                const float* __restrict__ W_ih,  // [3H] (I=1)
                const float* __restrict__ W_hh,  // [3H,H]
                const float* __restrict__ b_ih,  // [3H]
                const float* __restrict__ b_hh,  // [3H]
                const float* __restrict__ W_out, // [H]
                const float* __restrict__ b_out, // [1]
                float* __restrict__ y,           // [B,T]
                float* __restrict__ hn,          // [B,H]
                int B, int T)
{
    __shared__ __align__(16) float ring[WPB][2][2 * RSTRIDE]; // double-buffered h, 2 rows
    __shared__ float hT[WPB][2][TSTRIDE];                     // per-row 32x17 history
    __shared__ float wout_s[H + 1];                           // [32]=b_out

    const int lane = threadIdx.x & 31;
    const int w    = threadIdx.x >> 5;
    const int npairs = B >> 1;
    const int p    = blockIdx.x * WPB + w;

    if (threadIdx.x < H) wout_s[threadIdx.x] = W_out[threadIdx.x];
    if (threadIdx.x == H) wout_s[H] = b_out[0];
    __syncthreads();
    if (p >= npairs) return;

    const int u0  = lane & 15;     // first hidden unit this lane owns
    const int r   = lane >> 4;     // which row of the pair this half-warp runs
    const int row = 2 * p + r;     // global batch row

    // ---- recurrent weights for units u0 and u0+16 (6 gate rows), packed pairs.
    //      r/z rows pre-scaled by 0.5: sigmoid(a) = 0.5 + 0.5*tanh(a/2). ----
    ull Wr0[16], Wz0[16], Wn0[16], Wr1[16], Wz1[16], Wn1[16];
    {
        const ull HALF2 = 0x3F0000003F000000ull;  // (0.5f, 0.5f)
        const int u1 = u0 + 16;
        const ull* wr0 = (const ull*)(W_hh + (size_t)u0 * H);
        const ull* wz0 = (const ull*)(W_hh + (size_t)(H + u0) * H);
        const ull* wn0 = (const ull*)(W_hh + (size_t)(2 * H + u0) * H);
        const ull* wr1 = (const ull*)(W_hh + (size_t)u1 * H);
        const ull* wz1 = (const ull*)(W_hh + (size_t)(H + u1) * H);
        const ull* wn1 = (const ull*)(W_hh + (size_t)(2 * H + u1) * H);
        #pragma unroll
        for (int k = 0; k < 16; k++) {
            Wr0[k] = mulf2(wr0[k], HALF2);
            Wz0[k] = mulf2(wz0[k], HALF2);
            Wn0[k] = wn0[k];
            Wr1[k] = mulf2(wr1[k], HALF2);
            Wz1[k] = mulf2(wz1[k], HALF2);
            Wn1[k] = wn1[k];
        }
    }
    const int u1 = u0 + 16;
    const float wihr0 = 0.5f * W_ih[u0],    wihr1 = 0.5f * W_ih[u1];
    const float wihz0 = 0.5f * W_ih[H + u0], wihz1 = 0.5f * W_ih[H + u1];
    const float wihn0 = W_ih[2 * H + u0],   wihn1 = W_ih[2 * H + u1];
    // ALL gate biases folded into accumulator inits (lo half of packed pair)
    const ull ir0 = pack2(0.5f * (b_ih[u0] + b_hh[u0]), 0.0f);
    const ull ir1 = pack2(0.5f * (b_ih[u1] + b_hh[u1]), 0.0f);
    const ull iz0 = pack2(0.5f * (b_ih[H + u0] + b_hh[H + u0]), 0.0f);
    const ull iz1 = pack2(0.5f * (b_ih[H + u1] + b_hh[H + u1]), 0.0f);
    const ull in0 = pack2(b_hh[2 * H + u0], 0.0f);   // n hidden bias (inside r*)
    const ull in1 = pack2(b_hh[2 * H + u1], 0.0f);
    const float bin0 = b_ih[2 * H + u0], bin1 = b_ih[2 * H + u1];

    float hA = h0[(size_t)row * H + u0];
    float hB = h0[(size_t)row * H + u1];
    ring[w][1][r * RSTRIDE + u0] = hA;     // step 0 reads parity 1
    ring[w][1][r * RSTRIDE + u1] = hB;
    __syncwarp();

    const float* xrow = x + (size_t)row * T;
    float*       yrow = y + (size_t)row * T;
    float* hTrow = &hT[w][r][0];

    float xv = xrow[u0];                   // first chunk's x, prefetched

    for (int t0 = 0; t0 < T; t0 += CHUNK) {
        #pragma unroll 4
        for (int s = 0; s < CHUNK; s++) {
            const int rd = (s & 1) ^ 1;
            const int wb = (s & 1);

            const float xt = __shfl_sync(0xffffffffu, xv, s, 16); // per-half bcast

            const ulonglong2* hp = (const ulonglong2*)&ring[w][rd][r * RSTRIDE];
            ull ar0 = ir0, az0 = iz0, an0 = in0;
            ull ar1 = ir1, az1 = iz1, an1 = in1;
            #pragma unroll
            for (int q = 0; q < 8; q++) {
                const ulonglong2 hv = hp[q];     // 4 h values of this row
                ar0 = ffma2(hv.x, Wr0[2 * q],     ar0);
                az0 = ffma2(hv.x, Wz0[2 * q],     az0);
                an0 = ffma2(hv.x, Wn0[2 * q],     an0);
                ar1 = ffma2(hv.x, Wr1[2 * q],     ar1);
                az1 = ffma2(hv.x, Wz1[2 * q],     az1);
                an1 = ffma2(hv.x, Wn1[2 * q],     an1);
                ar0 = ffma2(hv.y, Wr0[2 * q + 1], ar0);
                az0 = ffma2(hv.y, Wz0[2 * q + 1], az0);
                an0 = ffma2(hv.y, Wn0[2 * q + 1], an0);
                ar1 = ffma2(hv.y, Wr1[2 * q + 1], ar1);
                az1 = ffma2(hv.y, Wz1[2 * q + 1], az1);
                an1 = ffma2(hv.y, Wn1[2 * q + 1], an1);
            }
            // unit u0
            {
                const float rg = fmaf(0.5f, tanh_ap(fmaf(xt, wihr0, hsum2(ar0))), 0.5f);
                const float zg = fmaf(0.5f, tanh_ap(fmaf(xt, wihz0, hsum2(az0))), 0.5f);
                const float ng = tanh_ap(fmaf(rg, hsum2(an0), fmaf(xt, wihn0, bin0)));
                hA = fmaf(zg, hA - ng, ng);
            }
            // unit u0+16
            {
                const float rg = fmaf(0.5f, tanh_ap(fmaf(xt, wihr1, hsum2(ar1))), 0.5f);
                const float zg = fmaf(0.5f, tanh_ap(fmaf(xt, wihz1, hsum2(az1))), 0.5f);
                const float ng = tanh_ap(fmaf(rg, hsum2(an1), fmaf(xt, wihn1, bin1)));
                hB = fmaf(zg, hB - ng, ng);
            }

            ring[w][wb][r * RSTRIDE + u0] = hA;
            ring[w][wb][r * RSTRIDE + u1] = hB;
            hTrow[17 * u0 + s] = hA;          // conflict-free (derived bank map)
            hTrow[17 * u1 + s] = hB;
            __syncwarp();
        }

        // Prefetch next chunk's x while the y-phase runs (hides LDG latency
        // that previously stalled step 0 of each chunk).
        float xv_nx = 0.0f;
        if (t0 + CHUNK < T) xv_nx = xrow[t0 + CHUNK + u0];

        // Deferred y: every lane produces one output (row r, timestep u0).
        float acc = wout_s[H];                // b_out folded into init
        #pragma unroll
        for (int j = 0; j < H; j++)
            acc = fmaf(hTrow[17 * j + u0], wout_s[j], acc);
        yrow[t0 + u0] = acc;                  // 2x64B coalesced, all lanes
        __syncwarp();                          // hT WAR before next chunk

        xv = xv_nx;
    }

    hn[(size_t)row * H + u0] = hA;
    hn[(size_t)row * H + u1] = hB;
}

extern "C" void kernel_launch(void* const* d_in, const int* in_sizes, int n_in,
                              void* d_out, int out_size) {
    const float* x     = (const float*)d_in[0];   // [B,T,1]
    const float* h0    = (const float*)d_in[1];   // [1,B,H]
    const float* W_ih  = (const float*)d_in[2];   // [3H,1]
    const float* W_hh  = (const float*)d_in[3];   // [3H,H]
    const float* b_ih  = (const float*)d_in[4];   // [3H]
    const float* b_hh  = (const float*)d_in[5];   // [3H]
    const float* W_out = (const float*)d_in[6];   // [1,H]
    const float* b_out = (const float*)d_in[7];   // [1]
    float* out = (float*)d_out;

    const int B = in_sizes[1] / H;                // 2048
    const int T = in_sizes[0] / B;                // 1024

    float* y  = out;                              // [B,T]
    float* hn = out + (size_t)B * T;              // [B,H]

    const int npairs = B / 2;                     // 1024
    const int grid = (npairs + WPB - 1) / WPB;    // 147 -> all SMs, single wave
    gru_warp_kernel<<<grid, THREADS>>>(x, h0, W_ih, W_hh, b_ih, b_hh,
                                       W_out, b_out, y, hn, B, T);
}

// round 12
// speedup vs baseline: 1.1319x; 1.0113x over previous
#include <cuda_runtime.h>

#define H 32
#define WPB 7            // warps per block; each warp = 2 batch rows
#define THREADS (WPB*32)
#define CHUNK 32         // deferred-output chunk (dynamic smem)
#define RSTRIDE 48       // ring: row B offset (floats) -> 16-bank shift
#define TSTR2R 1072      // hT: row B offset within warp (1072%32==16)
#define HT_WSTR 2144     // hT: per-warp stride (2144%32==0, pattern preserved)

// dynamic smem layout (floats):
//   [0, 1344)        ring  [WPB][2][2*RSTRIDE]
//   [1344, 1377)     wout  [H+1] ([32]=b_out)
//   [1392, 16400)    hT    per warp HT_WSTR, per row TSTR2R, unit stride 33
#define RING_OFF 0
#define WOUT_OFF 1344
#define HT_OFF   1392
#define SMEM_FLOATS 16400
#define SMEM_BYTES (SMEM_FLOATS * 4)

typedef unsigned long long ull;

// ---------- packed f32x2 helpers (sm_103a dual FP32 pipe) ----------
__device__ __forceinline__ ull ffma2(ull a, ull b, ull c) {
    ull d;
    asm("fma.rn.f32x2 %0, %1, %2, %3;" : "=l"(d) : "l"(a), "l"(b), "l"(c));
    return d;
}
__device__ __forceinline__ ull mulf2(ull a, ull b) {
    ull d;
    asm("mul.rn.f32x2 %0, %1, %2;" : "=l"(d) : "l"(a), "l"(b));
    return d;
}
__device__ __forceinline__ float hsum2(ull a) {
    float lo, hi;
    asm("mov.b64 {%0, %1}, %2;" : "=f"(lo), "=f"(hi) : "l"(a));
    return lo + hi;
}
__device__ __forceinline__ float tanh_ap(float x) {
    float r; asm("tanh.approx.f32 %0, %1;" : "=f"(r) : "f"(x)); return r;
}
__device__ __forceinline__ ull pack2(float lo, float hi) {
    ull d;
    asm("mov.b64 %0, {%1, %2};" : "=l"(d) : "f"(lo), "f"(hi));
    return d;
}

// One warp = 2 batch rows (half-warp per row); lane owns hidden units u0, u0+16
// of its row. grid=147 x 7 warps covers 1024 row-pairs, single wave, all SMs.
__global__ void __launch_bounds__(THREADS, 1)
gru_warp_kernel(const float* __restrict__ x,     // [B,T]
                const float* __restrict__ h0,    // [B,H]
                const float* __restrict__ W_ih,  // [3H] (I=1)
                const float* __restrict__ W_hh,  // [3H,H]
                const float* __restrict__ b_ih,  // [3H]
                const float* __restrict__ b_hh,  // [3H]
                const float* __restrict__ W_out, // [H]
                const float* __restrict__ b_out, // [1]
                float* __restrict__ y,           // [B,T]
                float* __restrict__ hn,          // [B,H]
                int B, int T)
{
    extern __shared__ __align__(16) float smem[];
    float* ring   = smem + RING_OFF;
    float* wout_s = smem + WOUT_OFF;
    float* hTall  = smem + HT_OFF;

    const int lane = threadIdx.x & 31;
    const int w    = threadIdx.x >> 5;
    const int npairs = B >> 1;
    const int p    = blockIdx.x * WPB + w;

    if (threadIdx.x < H) wout_s[threadIdx.x] = W_out[threadIdx.x];
    if (threadIdx.x == H) wout_s[H] = b_out[0];
    __syncthreads();
    if (p >= npairs) return;

    const int u0  = lane & 15;     // first hidden unit this lane owns
    const int r   = lane >> 4;     // which row of the pair this half-warp runs
    const int row = 2 * p + r;     // global batch row

    // ---- recurrent weights for units u0 and u0+16 (6 gate rows), packed pairs.
    //      r/z rows pre-scaled by 0.5: sigmoid(a) = 0.5 + 0.5*tanh(a/2). ----
    ull Wr0[16], Wz0[16], Wn0[16], Wr1[16], Wz1[16], Wn1[16];
    {
        const ull HALF2 = 0x3F0000003F000000ull;  // (0.5f, 0.5f)
        const int u1 = u0 + 16;
        const ull* wr0 = (const ull*)(W_hh + (size_t)u0 * H);
        const ull* wz0 = (const ull*)(W_hh + (size_t)(H + u0) * H);
        const ull* wn0 = (const ull*)(W_hh + (size_t)(2 * H + u0) * H);
        const ull* wr1 = (const ull*)(W_hh + (size_t)u1 * H);
        const ull* wz1 = (const ull*)(W_hh + (size_t)(H + u1) * H);
        const ull* wn1 = (const ull*)(W_hh + (size_t)(2 * H + u1) * H);
        #pragma unroll
        for (int k = 0; k < 16; k++) {
            Wr0[k] = mulf2(wr0[k], HALF2);
            Wz0[k] = mulf2(wz0[k], HALF2);
            Wn0[k] = wn0[k];
            Wr1[k] = mulf2(wr1[k], HALF2);
            Wz1[k] = mulf2(wz1[k], HALF2);
            Wn1[k] = wn1[k];
        }
    }
    const int u1 = u0 + 16;
    const float wihr0 = 0.5f * W_ih[u0],    wihr1 = 0.5f * W_ih[u1];
    const float wihz0 = 0.5f * W_ih[H + u0], wihz1 = 0.5f * W_ih[H + u1];
    const float wihn0 = W_ih[2 * H + u0],   wihn1 = W_ih[2 * H + u1];
    // ALL gate biases folded into accumulator inits (lo half of packed pair)
    const ull ir0 = pack2(0.5f * (b_ih[u0] + b_hh[u0]), 0.0f);
    const ull ir1 = pack2(0.5f * (b_ih[u1] + b_hh[u1]), 0.0f);
    const ull iz0 = pack2(0.5f * (b_ih[H + u0] + b_hh[H + u0]), 0.0f);
    const ull iz1 = pack2(0.5f * (b_ih[H + u1] + b_hh[H + u1]), 0.0f);
    const ull in0 = pack2(b_hh[2 * H + u0], 0.0f);   // n hidden bias (inside r*)
    const ull in1 = pack2(b_hh[2 * H + u1], 0.0f);
    const float bin0 = b_ih[2 * H + u0], bin1 = b_ih[2 * H + u1];

    float* ringw = ring + w * (2 * 2 * RSTRIDE);     // [2][96]
    float* hTrow = hTall + w * HT_WSTR + r * TSTR2R; // this row's 32x33 history

    float hA = h0[(size_t)row * H + u0];
    float hB = h0[(size_t)row * H + u1];
    ringw[96 + r * RSTRIDE + u0] = hA;     // step 0 reads parity 1
    ringw[96 + r * RSTRIDE + u1] = hB;
    __syncwarp();

    const float* xrow = x + (size_t)row * T;
    float*       yrow = y + (size_t)row * T;

    float xv0 = xrow[u0];                  // first chunk x, steps 0..15
    float xv1 = xrow[16 + u0];             // first chunk x, steps 16..31

    for (int t0 = 0; t0 < T; t0 += CHUNK) {
        #pragma unroll 2
        for (int s = 0; s < CHUNK; s++) {
            const int rd = (s & 1) ^ 1;
            const int wb = (s & 1);

            const float xsrc = (s & 16) ? xv1 : xv0;
            const float xt = __shfl_sync(0xffffffffu, xsrc, s & 15, 16);

            const ulonglong2* hp = (const ulonglong2*)&ringw[rd * 96 + r * RSTRIDE];
            ull ar0 = ir0, az0 = iz0, an0 = in0;
            ull ar1 = ir1, az1 = iz1, an1 = in1;
            #pragma unroll
            for (int q = 0; q < 8; q++) {
                const ulonglong2 hv = hp[q];     // 4 h values of this row
                ar0 = ffma2(hv.x, Wr0[2 * q],     ar0);
                az0 = ffma2(hv.x, Wz0[2 * q],     az0);
                an0 = ffma2(hv.x, Wn0[2 * q],     an0);
                ar1 = ffma2(hv.x, Wr1[2 * q],     ar1);
                az1 = ffma2(hv.x, Wz1[2 * q],     az1);
                an1 = ffma2(hv.x, Wn1[2 * q],     an1);
                ar0 = ffma2(hv.y, Wr0[2 * q + 1], ar0);
                az0 = ffma2(hv.y, Wz0[2 * q + 1], az0);
                an0 = ffma2(hv.y, Wn0[2 * q + 1], an0);
                ar1 = ffma2(hv.y, Wr1[2 * q + 1], ar1);
                az1 = ffma2(hv.y, Wz1[2 * q + 1], az1);
                an1 = ffma2(hv.y, Wn1[2 * q + 1], an1);
            }
            // unit u0
            {
                const float rg = fmaf(0.5f, tanh_ap(fmaf(xt, wihr0, hsum2(ar0))), 0.5f);
                const float zg = fmaf(0.5f, tanh_ap(fmaf(xt, wihz0, hsum2(az0))), 0.5f);
                const float ng = tanh_ap(fmaf(rg, hsum2(an0), fmaf(xt, wihn0, bin0)));
                hA = fmaf(zg, hA - ng, ng);
            }
            // unit u0+16
            {
                const float rg = fmaf(0.5f, tanh_ap(fmaf(xt, wihr1, hsum2(ar1))), 0.5f);
                const float zg = fmaf(0.5f, tanh_ap(fmaf(xt, wihz1, hsum2(az1))), 0.5f);
                const float ng = tanh_ap(fmaf(rg, hsum2(an1), fmaf(xt, wihn1, bin1)));
                hB = fmaf(zg, hB - ng, ng);
            }

            ringw[wb * 96 + r * RSTRIDE + u0] = hA;
            ringw[wb * 96 + r * RSTRIDE + u1] = hB;
            hTrow[33 * u0 + s] = hA;          // conflict-free (derived bank map)
            hTrow[33 * u1 + s] = hB;
            __syncwarp();
        }

        // Prefetch next chunk's x while the y-phase runs.
        float xn0 = 0.0f, xn1 = 0.0f;
        if (t0 + CHUNK < T) {
            xn0 = xrow[t0 + CHUNK + u0];
            xn1 = xrow[t0 + CHUNK + 16 + u0];
        }

        // Deferred y: each lane produces 2 outputs (row r, steps u0 and u0+16),
        // 4 independent 16-deep FMA chains to cut exposed latency.
        float a0 = wout_s[H], a1 = wout_s[H];   // b_out folded into init
        float b0 = 0.0f,      b1 = 0.0f;
        #pragma unroll
        for (int j = 0; j < 16; j++) {
            a0 = fmaf(hTrow[33 * j + u0],            wout_s[j],      a0);
            a1 = fmaf(hTrow[33 * j + u0 + 16],       wout_s[j],      a1);
            b0 = fmaf(hTrow[33 * (j + 16) + u0],     wout_s[j + 16], b0);
            b1 = fmaf(hTrow[33 * (j + 16) + u0 + 16], wout_s[j + 16], b1);
        }
        yrow[t0 + u0]      = a0 + b0;         // coalesced per half-warp
        yrow[t0 + u0 + 16] = a1 + b1;
        __syncwarp();                          // hT WAR before next chunk

        xv0 = xn0;
        xv1 = xn1;
    }

    hn[(size_t)row * H + u0] = hA;
    hn[(size_t)row * H + u1] = hB;
}

extern "C" void kernel_launch(void* const* d_in, const int* in_sizes, int n_in,
                              void* d_out, int out_size) {
    const float* x     = (const float*)d_in[0];   // [B,T,1]
    const float* h0    = (const float*)d_in[1];   // [1,B,H]
    const float* W_ih  = (const float*)d_in[2];   // [3H,1]
    const float* W_hh  = (const float*)d_in[3];   // [3H,H]
    const float* b_ih  = (const float*)d_in[4];   // [3H]
    const float* b_hh  = (const float*)d_in[5];   // [3H]
    const float* W_out = (const float*)d_in[6];   // [1,H]
    const float* b_out = (const float*)d_in[7];   // [1]
    float* out = (float*)d_out;

    const int B = in_sizes[1] / H;                // 2048
    const int T = in_sizes[0] / B;                // 1024

    float* y  = out;                              // [B,T]
    float* hn = out + (size_t)B * T;              // [B,H]

    static bool attr_set = false;                 // idempotent; safe pre-capture
    if (!attr_set) {
        cudaFuncSetAttribute(gru_warp_kernel,
                             cudaFuncAttributeMaxDynamicSharedMemorySize,
                             SMEM_BYTES);
        attr_set = true;
    }

    const int npairs = B / 2;                     // 1024
    const int grid = (npairs + WPB - 1) / WPB;    // 147 -> all SMs, single wave
    gru_warp_kernel<<<grid, THREADS, SMEM_BYTES>>>(x, h0, W_ih, W_hh, b_ih, b_hh,
                                                   W_out, b_out, y, hn, B, T);
}

// round 13
// speedup vs baseline: 1.1367x; 1.0042x over previous
#include <cuda_runtime.h>

#define H 32
#define WPB 7            // warps per block; each warp = 2 batch rows
#define THREADS (WPB*32)
#define CHUNK 32         // deferred-output chunk (dynamic smem)
#define RSTRIDE 48       // ring: row B offset (floats) -> 16-bank shift
#define TSTR2R 1072      // hT: row B offset within warp (1072%32==16)
#define HT_WSTR 2144     // hT: per-warp stride (2144%32==0, pattern preserved)

// dynamic smem layout (floats):
//   [0, 1344)        ring  [WPB][2][2*RSTRIDE]
//   [1344, 1377)     wout  [H+1] ([32]=b_out)
//   [1392, 16400)    hT    per warp HT_WSTR, per row TSTR2R, unit stride 33
#define RING_OFF 0
#define WOUT_OFF 1344
#define HT_OFF   1392
#define SMEM_FLOATS 16400
#define SMEM_BYTES (SMEM_FLOATS * 4)

typedef unsigned long long ull;

// zero-instruction ordering fence: same-warp MIO is processed in issue order,
// so only the COMPILER must be stopped from reordering smem accesses.
// (R9 empirically confirmed correctness of syncwarp-free stepping: identical
// rel_err to the barrier version.)
#define CFENCE() asm volatile("" ::: "memory")

// ---------- packed f32x2 helpers (sm_103a dual FP32 pipe) ----------
__device__ __forceinline__ ull ffma2(ull a, ull b, ull c) {
    ull d;
    asm("fma.rn.f32x2 %0, %1, %2, %3;" : "=l"(d) : "l"(a), "l"(b), "l"(c));
    return d;
}
__device__ __forceinline__ ull mulf2(ull a, ull b) {
    ull d;
    asm("mul.rn.f32x2 %0, %1, %2;" : "=l"(d) : "l"(a), "l"(b));
    return d;
}
__device__ __forceinline__ float hsum2(ull a) {
    float lo, hi;
    asm("mov.b64 {%0, %1}, %2;" : "=f"(lo), "=f"(hi) : "l"(a));
    return lo + hi;
}
__device__ __forceinline__ float tanh_ap(float x) {
    float r; asm("tanh.approx.f32 %0, %1;" : "=f"(r) : "f"(x)); return r;
}
__device__ __forceinline__ ull pack2(float lo, float hi) {
    ull d;
    asm("mov.b64 %0, {%1, %2};" : "=l"(d) : "f"(lo), "f"(hi));
    return d;
}

// One warp = 2 batch rows (half-warp per row); lane owns hidden units u0, u0+16
// of its row. grid=147 x 7 warps covers 1024 row-pairs, single wave, all SMs.
__global__ void __launch_bounds__(THREADS, 1)
gru_warp_kernel(const float* __restrict__ x,     // [B,T]
                const float* __restrict__ h0,    // [B,H]
                const float* __restrict__ W_ih,  // [3H] (I=1)
                const float* __restrict__ W_hh,  // [3H,H]
                const float* __restrict__ b_ih,  // [3H]
                const float* __restrict__ b_hh,  // [3H]
                const float* __restrict__ W_out, // [H]
                const float* __restrict__ b_out, // [1]
                float* __restrict__ y,           // [B,T]
                float* __restrict__ hn,          // [B,H]
                int B, int T)
{
    extern __shared__ __align__(16) float smem[];
    float* ring   = smem + RING_OFF;
    float* wout_s = smem + WOUT_OFF;
    float* hTall  = smem + HT_OFF;

    const int lane = threadIdx.x & 31;
    const int w    = threadIdx.x >> 5;
    const int npairs = B >> 1;
    const int p    = blockIdx.x * WPB + w;

    if (threadIdx.x < H) wout_s[threadIdx.x] = W_out[threadIdx.x];
    if (threadIdx.x == H) wout_s[H] = b_out[0];
    __syncthreads();
    if (p >= npairs) return;

    const int u0  = lane & 15;     // first hidden unit this lane owns
    const int r   = lane >> 4;     // which row of the pair this half-warp runs
    const int row = 2 * p + r;     // global batch row

    // ---- recurrent weights for units u0 and u0+16 (6 gate rows), packed pairs.
    //      r/z rows pre-scaled by 0.5: sigmoid(a) = 0.5 + 0.5*tanh(a/2). ----
    ull Wr0[16], Wz0[16], Wn0[16], Wr1[16], Wz1[16], Wn1[16];
    {
        const ull HALF2 = 0x3F0000003F000000ull;  // (0.5f, 0.5f)
        const int u1 = u0 + 16;
        const ull* wr0 = (const ull*)(W_hh + (size_t)u0 * H);
        const ull* wz0 = (const ull*)(W_hh + (size_t)(H + u0) * H);
        const ull* wn0 = (const ull*)(W_hh + (size_t)(2 * H + u0) * H);
        const ull* wr1 = (const ull*)(W_hh + (size_t)u1 * H);
        const ull* wz1 = (const ull*)(W_hh + (size_t)(H + u1) * H);
        const ull* wn1 = (const ull*)(W_hh + (size_t)(2 * H + u1) * H);
        #pragma unroll
        for (int k = 0; k < 16; k++) {
            Wr0[k] = mulf2(wr0[k], HALF2);
            Wz0[k] = mulf2(wz0[k], HALF2);
            Wn0[k] = wn0[k];
            Wr1[k] = mulf2(wr1[k], HALF2);
            Wz1[k] = mulf2(wz1[k], HALF2);
            Wn1[k] = wn1[k];
        }
    }
    const int u1 = u0 + 16;
    const float wihr0 = 0.5f * W_ih[u0],    wihr1 = 0.5f * W_ih[u1];
    const float wihz0 = 0.5f * W_ih[H + u0], wihz1 = 0.5f * W_ih[H + u1];
    const float wihn0 = W_ih[2 * H + u0],   wihn1 = W_ih[2 * H + u1];
    // ALL gate biases folded into accumulator inits (lo half of packed pair)
    const ull ir0 = pack2(0.5f * (b_ih[u0] + b_hh[u0]), 0.0f);
    const ull ir1 = pack2(0.5f * (b_ih[u1] + b_hh[u1]), 0.0f);
    const ull iz0 = pack2(0.5f * (b_ih[H + u0] + b_hh[H + u0]), 0.0f);
    const ull iz1 = pack2(0.5f * (b_ih[H + u1] + b_hh[H + u1]), 0.0f);
    const ull in0 = pack2(b_hh[2 * H + u0], 0.0f);   // n hidden bias (inside r*)
    const ull in1 = pack2(b_hh[2 * H + u1], 0.0f);
    const float bin0 = b_ih[2 * H + u0], bin1 = b_ih[2 * H + u1];

    float* ringw = ring + w * (2 * 2 * RSTRIDE);     // [2][96]
    float* hTrow = hTall + w * HT_WSTR + r * TSTR2R; // this row's 32x33 history

    float hA = h0[(size_t)row * H + u0];
    float hB = h0[(size_t)row * H + u1];
    ringw[96 + r * RSTRIDE + u0] = hA;     // step 0 reads parity 1
    ringw[96 + r * RSTRIDE + u1] = hB;
    __syncwarp();

    const float* xrow = x + (size_t)row * T;
    float*       yrow = y + (size_t)row * T;

    float xv0 = xrow[u0];                  // first chunk x, steps 0..15
    float xv1 = xrow[16 + u0];             // first chunk x, steps 16..31

    for (int t0 = 0; t0 < T; t0 += CHUNK) {
        #pragma unroll 2
        for (int s = 0; s < CHUNK; s++) {
            const int rd = (s & 1) ^ 1;
            const int wb = (s & 1);

            const float xsrc = (s & 16) ? xv1 : xv0;
            const float xt = __shfl_sync(0xffffffffu, xsrc, s & 15, 16);

            const ulonglong2* hp = (const ulonglong2*)&ringw[rd * 96 + r * RSTRIDE];
            ull ar0 = ir0, az0 = iz0, an0 = in0;
            ull ar1 = ir1, az1 = iz1, an1 = in1;
            #pragma unroll
            for (int q = 0; q < 8; q++) {
                const ulonglong2 hv = hp[q];     // 4 h values of this row
                ar0 = ffma2(hv.x, Wr0[2 * q],     ar0);
                az0 = ffma2(hv.x, Wz0[2 * q],     az0);
                an0 = ffma2(hv.x, Wn0[2 * q],     an0);
                ar1 = ffma2(hv.x, Wr1[2 * q],     ar1);
                az1 = ffma2(hv.x, Wz1[2 * q],     az1);
                an1 = ffma2(hv.x, Wn1[2 * q],     an1);
                ar0 = ffma2(hv.y, Wr0[2 * q + 1], ar0);
                az0 = ffma2(hv.y, Wz0[2 * q + 1], az0);
                an0 = ffma2(hv.y, Wn0[2 * q + 1], an0);
                ar1 = ffma2(hv.y, Wr1[2 * q + 1], ar1);
                az1 = ffma2(hv.y, Wz1[2 * q + 1], az1);
                an1 = ffma2(hv.y, Wn1[2 * q + 1], an1);
            }
            // unit u0
            {
                const float rg = fmaf(0.5f, tanh_ap(fmaf(xt, wihr0, hsum2(ar0))), 0.5f);
                const float zg = fmaf(0.5f, tanh_ap(fmaf(xt, wihz0, hsum2(az0))), 0.5f);
                const float ng = tanh_ap(fmaf(rg, hsum2(an0), fmaf(xt, wihn0, bin0)));
                hA = fmaf(zg, hA - ng, ng);
            }
            // unit u0+16
            {
                const float rg = fmaf(0.5f, tanh_ap(fmaf(xt, wihr1, hsum2(ar1))), 0.5f);
                const float zg = fmaf(0.5f, tanh_ap(fmaf(xt, wihz1, hsum2(az1))), 0.5f);
                const float ng = tanh_ap(fmaf(rg, hsum2(an1), fmaf(xt, wihn1, bin1)));
                hB = fmaf(zg, hB - ng, ng);
            }

            ringw[wb * 96 + r * RSTRIDE + u0] = hA;
            ringw[wb * 96 + r * RSTRIDE + u1] = hB;
            hTrow[33 * u0 + s] = hA;          // conflict-free (derived bank map)
            hTrow[33 * u1 + s] = hB;
            CFENCE();         // same-warp in-order MIO: no WARPSYNC needed
        }

        // Prefetch next chunk's x while the y-phase runs.
        float xn0 = 0.0f, xn1 = 0.0f;
        if (t0 + CHUNK < T) {
            xn0 = xrow[t0 + CHUNK + u0];
            xn1 = xrow[t0 + CHUNK + 16 + u0];
        }

        // Deferred y: each lane produces 2 outputs (row r, steps u0 and u0+16),
        // 4 independent 16-deep FMA chains to cut exposed latency.
        float a0 = wout_s[H], a1 = wout_s[H];   // b_out folded into init
        float b0 = 0.0f,      b1 = 0.0f;
        #pragma unroll
        for (int j = 0; j < 16; j++) {
            a0 = fmaf(hTrow[33 * j + u0],            wout_s[j],      a0);
            a1 = fmaf(hTrow[33 * j + u0 + 16],       wout_s[j],      a1);
            b0 = fmaf(hTrow[33 * (j + 16) + u0],     wout_s[j + 16], b0);
            b1 = fmaf(hTrow[33 * (j + 16) + u0 + 16], wout_s[j + 16], b1);
        }
        yrow[t0 + u0]      = a0 + b0;         // coalesced per half-warp
        yrow[t0 + u0 + 16] = a1 + b1;
        __syncwarp();                          // hT WAR guard, 1 per 32 steps

        xv0 = xn0;
        xv1 = xn1;
    }

    hn[(size_t)row * H + u0] = hA;
    hn[(size_t)row * H + u1] = hB;
}

extern "C" void kernel_launch(void* const* d_in, const int* in_sizes, int n_in,
                              void* d_out, int out_size) {
    const float* x     = (const float*)d_in[0];   // [B,T,1]
    const float* h0    = (const float*)d_in[1];   // [1,B,H]
    const float* W_ih  = (const float*)d_in[2];   // [3H,1]
    const float* W_hh  = (const float*)d_in[3];   // [3H,H]
    const float* b_ih  = (const float*)d_in[4];   // [3H]
    const float* b_hh  = (const float*)d_in[5];   // [3H]
    const float* W_out = (const float*)d_in[6];   // [1,H]
    const float* b_out = (const float*)d_in[7];   // [1]
    float* out = (float*)d_out;

    const int B = in_sizes[1] / H;                // 2048
    const int T = in_sizes[0] / B;                // 1024

    float* y  = out;                              // [B,T]
    float* hn = out + (size_t)B * T;              // [B,H]

    static bool attr_set = false;                 // idempotent; safe pre-capture
    if (!attr_set) {
        cudaFuncSetAttribute(gru_warp_kernel,
                             cudaFuncAttributeMaxDynamicSharedMemorySize,
                             SMEM_BYTES);
        attr_set = true;
    }

    const int npairs = B / 2;                     // 1024
    const int grid = (npairs + WPB - 1) / WPB;    // 147 -> all SMs, single wave
    gru_warp_kernel<<<grid, THREADS, SMEM_BYTES>>>(x, h0, W_ih, W_hh, b_ih, b_hh,
                                                   W_out, b_out, y, hn, B, T);
}